// round 7
// baseline (speedup 1.0000x reference)
#include <cuda_runtime.h>

#define NUM_LINK 9
#define DOF 7

// 256-bit streaming store: 8 consecutive floats (sm_100a).
__device__ __forceinline__ void stcs_f8(float* p,
                                        float4 a, float4 b) {
    asm volatile("st.global.cs.v8.f32 [%0], {%1,%2,%3,%4,%5,%6,%7,%8};"
                 :: "l"(p),
                    "f"(a.x), "f"(a.y), "f"(a.z), "f"(a.w),
                    "f"(b.x), "f"(b.y), "f"(b.z), "f"(b.w)
                 : "memory");
}

// Forward kinematics, 2 threads per robot — each thread owns TWO 4x4 rows
// (rows 2*sub and 2*sub+1) and drains them with one 256-bit store per link.
// Row independence: T' = T @ M computes row r from row r only.
__global__ __launch_bounds__(256)
void fk_kernel(const float* __restrict__ Tbase,
               const float* __restrict__ Toff,
               const float* __restrict__ Q,
               float* __restrict__ out,
               int B)
{
    __shared__ float4 sToff[NUM_LINK * 4];
    if (threadIdx.x < NUM_LINK * 4)
        sToff[threadIdx.x] = reinterpret_cast<const float4*>(Toff)[threadIdx.x];
    __syncthreads();

    int g   = blockIdx.x * blockDim.x + threadIdx.x;
    int b   = g >> 1;           // robot index
    int sub = g & 1;            // row-pair index: rows 2*sub, 2*sub+1
    bool valid = (b < B);
    int bb = valid ? b : (B - 1);   // clamp so shfl participation is uniform

    // Load my two rows of Tbase (contiguous 32B per thread; warp spans 1KB).
    const float4* tb = reinterpret_cast<const float4*>(Tbase) + (size_t)bb * 4;
    float4 ra = tb[2 * sub + 0];
    float4 rb = tb[2 * sub + 1];

    // sincos split over the 2 lanes of this robot: lane s -> joints s, s+2,
    // s+4, s+6 (lane 1's 4th slot is a dummy). Exchange via shfl(width=2).
    const float* qb = Q + (size_t)bb * DOF;
    float sv[4], cv[4];
    #pragma unroll
    for (int k = 0; k < 4; k++) {
        int j = 2 * k + sub;
        __sincosf(qb[j < DOF ? j : 0], &sv[k], &cv[k]);
    }
    float sj[DOF], cj[DOF];
    #pragma unroll
    for (int j = 0; j < DOF; j++) {
        sj[j] = __shfl_sync(0xFFFFFFFFu, sv[j >> 1], j & 1, 2);
        cj[j] = __shfl_sync(0xFFFFFFFFu, cv[j >> 1], j & 1, 2);
    }

    float* outb = out + (size_t)b * (NUM_LINK * 16) + sub * 8;

    #pragma unroll
    for (int i = 0; i < NUM_LINK; i++) {
        // rows = rows @ Toff[i] (two independent row-vector x 4x4 products)
        float4 o0 = sToff[i * 4 + 0];
        float4 o1 = sToff[i * 4 + 1];
        float4 o2 = sToff[i * 4 + 2];
        float4 o3 = sToff[i * 4 + 3];
        float4 na, nb;
        na.x = fmaf(ra.x, o0.x, fmaf(ra.y, o1.x, fmaf(ra.z, o2.x, ra.w * o3.x)));
        nb.x = fmaf(rb.x, o0.x, fmaf(rb.y, o1.x, fmaf(rb.z, o2.x, rb.w * o3.x)));
        na.y = fmaf(ra.x, o0.y, fmaf(ra.y, o1.y, fmaf(ra.z, o2.y, ra.w * o3.y)));
        nb.y = fmaf(rb.x, o0.y, fmaf(rb.y, o1.y, fmaf(rb.z, o2.y, rb.w * o3.y)));
        na.z = fmaf(ra.x, o0.z, fmaf(ra.y, o1.z, fmaf(ra.z, o2.z, ra.w * o3.z)));
        nb.z = fmaf(rb.x, o0.z, fmaf(rb.y, o1.z, fmaf(rb.z, o2.z, rb.w * o3.z)));
        na.w = fmaf(ra.x, o0.w, fmaf(ra.y, o1.w, fmaf(ra.z, o2.w, ra.w * o3.w)));
        nb.w = fmaf(rb.x, o0.w, fmaf(rb.y, o1.w, fmaf(rb.z, o2.w, rb.w * o3.w)));
        ra = na; rb = nb;

        // Revolute joint at links 1..7 (axes z,y,z,y,z,y,z): mixes two columns.
        if (i >= 1 && i <= 7) {
            float s = sj[i - 1], c = cj[i - 1];
            if (i & 1) {        // z: col0' = c*x + s*y ; col1' = c*y - s*x
                float xa = ra.x, ya = ra.y, xb = rb.x, yb = rb.y;
                ra.x = fmaf(c, xa,  s * ya);  ra.y = fmaf(c, ya, -s * xa);
                rb.x = fmaf(c, xb,  s * yb);  rb.y = fmaf(c, yb, -s * xb);
            } else {            // y: col0' = c*x - s*z ; col2' = c*z + s*x
                float xa = ra.x, za = ra.z, xb = rb.x, zb = rb.z;
                ra.x = fmaf(c, xa, -s * za);  ra.z = fmaf(c, za,  s * xa);
                rb.x = fmaf(c, xb, -s * zb);  rb.z = fmaf(c, zb,  s * xb);
            }
        }

        // One 256-bit streaming store per link per thread (32B contiguous;
        // the robot's two lanes cover the full 64B link block).
        if (valid)
            stcs_f8(outb + i * 16, ra, rb);
    }
}

extern "C" void kernel_launch(void* const* d_in, const int* in_sizes, int n_in,
                              void* d_out, int out_size)
{
    int B = out_size / (NUM_LINK * 16);

    const float* Tbase = nullptr;
    const float* Toff  = nullptr;
    const float* Q     = nullptr;
    for (int i = 0; i < n_in; i++) {
        if (in_sizes[i] == NUM_LINK * 16)      Toff  = (const float*)d_in[i];
        else if (in_sizes[i] == B * 16)        Tbase = (const float*)d_in[i];
        else if (in_sizes[i] == B * DOF)       Q     = (const float*)d_in[i];
    }
    if (!Tbase) Tbase = (const float*)d_in[0];
    if (!Toff)  Toff  = (const float*)d_in[1];
    if (!Q)     Q     = (const float*)d_in[2];

    float* out = (float*)d_out;

    const int threads = 256;
    long long total = (long long)B * 2;
    const int blocks = (int)((total + threads - 1) / threads);
    fk_kernel<<<blocks, threads>>>(Tbase, Toff, Q, out, B);
}

// round 9
// speedup vs baseline: 1.0691x; 1.0691x over previous
#include <cuda_runtime.h>

#define NUM_LINK 9
#define DOF 7

__device__ __forceinline__ void stcs_f4(float* p, float4 v) {
    asm volatile("st.global.cs.v4.f32 [%0], {%1,%2,%3,%4};"
                 :: "l"(p), "f"(v.x), "f"(v.y), "f"(v.z), "f"(v.w) : "memory");
}

// Forward kinematics, 4 threads per robot — one 4x4-matrix ROW per thread.
// Row independence: for T' = T @ M, row r of T' depends only on row r of T.
// Joints at links 1..7, axes z,y,z,y,z,y,z (links 0 and 8 fixed).
// Output stores evict-first (.cs): the 288MB write stream is the DRAM-bound
// component; inputs stay L2-resident across graph replays.
__global__ __launch_bounds__(256)
void fk_kernel(const float* __restrict__ Tbase,
               const float* __restrict__ Toff,
               const float* __restrict__ Q,
               float* __restrict__ out,
               int B)
{
    __shared__ float4 sToff[NUM_LINK * 4];
    if (threadIdx.x < NUM_LINK * 4)
        sToff[threadIdx.x] = reinterpret_cast<const float4*>(Toff)[threadIdx.x];
    __syncthreads();

    int g   = blockIdx.x * blockDim.x + threadIdx.x;
    int b   = g >> 2;           // robot index
    int sub = g & 3;            // row index 0..3
    bool valid = (b < B);
    int bb = valid ? b : (B - 1);   // clamp so shfl participation is uniform

    // Coalesced Tbase row load (warp covers contiguous 512B).
    float4 r = reinterpret_cast<const float4*>(Tbase)[(size_t)bb * 4 + sub];

    // sincos split across the 4 lanes of this robot: lane t -> joints t, t+4.
    const float* qb = Q + (size_t)bb * DOF;
    float s_lo, c_lo, s_hi, c_hi;
    __sincosf(qb[sub], &s_lo, &c_lo);
    __sincosf(qb[sub < 3 ? sub + 4 : 3], &s_hi, &c_hi);  // lane 3 hi unused

    float sj[DOF], cj[DOF];
    #pragma unroll
    for (int j = 0; j < 4; j++) {
        sj[j] = __shfl_sync(0xFFFFFFFFu, s_lo, j, 4);
        cj[j] = __shfl_sync(0xFFFFFFFFu, c_lo, j, 4);
    }
    #pragma unroll
    for (int j = 4; j < DOF; j++) {
        sj[j] = __shfl_sync(0xFFFFFFFFu, s_hi, j - 4, 4);
        cj[j] = __shfl_sync(0xFFFFFFFFu, c_hi, j - 4, 4);
    }

    float* outb = out + (size_t)b * (NUM_LINK * 16) + sub * 4;

    #pragma unroll
    for (int i = 0; i < NUM_LINK; i++) {
        // r = r @ Toff[i]  (row-vector times 4x4; rows broadcast from smem)
        float4 o0 = sToff[i * 4 + 0];
        float4 o1 = sToff[i * 4 + 1];
        float4 o2 = sToff[i * 4 + 2];
        float4 o3 = sToff[i * 4 + 3];
        float4 n;
        n.x = fmaf(r.x, o0.x, fmaf(r.y, o1.x, fmaf(r.z, o2.x, r.w * o3.x)));
        n.y = fmaf(r.x, o0.y, fmaf(r.y, o1.y, fmaf(r.z, o2.y, r.w * o3.y)));
        n.z = fmaf(r.x, o0.z, fmaf(r.y, o1.z, fmaf(r.z, o2.z, r.w * o3.z)));
        n.w = fmaf(r.x, o0.w, fmaf(r.y, o1.w, fmaf(r.z, o2.w, r.w * o3.w)));
        r = n;

        // Revolute joint at links 1..7 (axes z,y,z,y,z,y,z): mixes two columns.
        if (i >= 1 && i <= 7) {
            float s = sj[i - 1], c = cj[i - 1];
            if (i & 1) {        // z: x' = c*x + s*y ; y' = c*y - s*x
                float x = r.x, y = r.y;
                r.x = fmaf(c, x,  s * y);
                r.y = fmaf(c, y, -s * x);
            } else {            // y: x' = c*x - s*z ; z' = c*z + s*x
                float x = r.x, z = r.z;
                r.x = fmaf(c, x, -s * z);
                r.z = fmaf(c, z,  s * x);
            }
        }

        // Store row sub of link i: lanes 4k..4k+3 = one contiguous 64B chunk.
        if (valid)
            stcs_f4(outb + i * 16, r);
    }
}

extern "C" void kernel_launch(void* const* d_in, const int* in_sizes, int n_in,
                              void* d_out, int out_size)
{
    int B = out_size / (NUM_LINK * 16);

    const float* Tbase = nullptr;
    const float* Toff  = nullptr;
    const float* Q     = nullptr;
    for (int i = 0; i < n_in; i++) {
        if (in_sizes[i] == NUM_LINK * 16)      Toff  = (const float*)d_in[i];
        else if (in_sizes[i] == B * 16)        Tbase = (const float*)d_in[i];
        else if (in_sizes[i] == B * DOF)       Q     = (const float*)d_in[i];
    }
    if (!Tbase) Tbase = (const float*)d_in[0];
    if (!Toff)  Toff  = (const float*)d_in[1];
    if (!Q)     Q     = (const float*)d_in[2];

    float* out = (float*)d_out;

    const int threads = 256;
    long long total = (long long)B * 4;
    const int blocks = (int)((total + threads - 1) / threads);
    fk_kernel<<<blocks, threads>>>(Tbase, Toff, Q, out, B);
}